// round 14
// baseline (speedup 1.0000x reference)
#include <cuda_runtime.h>

// ChronoRotationTransflormation: per-row normalized complex inner product.
// Inputs: head_real, head_imag, rel_real, rel_imag, tail_real, tail_imag
// all float32 [8192, 2048]. Output: float32 [8192].
//
// R12: persistent grid-stride CTAs (grid=592) with register double-buffer
// prefetch: next row's 6 LDG.128 are issued BEFORE the current row's
// reduction tail, so the SM-wide load stream never drains and there are no
// fresh-CTA wave transitions. 512 threads/CTA, one float4/thread/array.
// Ping-pong smem buffers -> one __syncthreads per row.

#define D 2048
#define DV (D / 4)          // 512 float4 per row
#define THREADS 512
#define WARPS (THREADS / 32)
#define ROWS 8192
#define GRID 592            // 148 SMs * 4 target CTAs

__global__ __launch_bounds__(THREADS)
void chrono_rot_kernel(const float4* __restrict__ hr,
                       const float4* __restrict__ hi,
                       const float4* __restrict__ rr,
                       const float4* __restrict__ ri,
                       const float4* __restrict__ tr,
                       const float4* __restrict__ ti,
                       float* __restrict__ out)
{
    const int tid = threadIdx.x;
    const int wid = tid >> 5;
    const int lid = tid & 31;
    const int stride = gridDim.x;

    __shared__ float s_ab[2][WARPS], s_aa[2][WARPS], s_bb[2][WARPS];

    int row = blockIdx.x;
    long long idx = (long long)row * DV + tid;

    // Prologue: load first row.
    float4 HR = __ldcs(hr + idx);
    float4 HI = __ldcs(hi + idx);
    float4 RR = __ldcs(rr + idx);
    float4 RI = __ldcs(ri + idx);
    float4 TR = __ldcs(tr + idx);
    float4 TI = __ldcs(ti + idx);

    int buf = 0;
    while (row < ROWS) {
        const int nrow = row + stride;
        const bool have_next = (nrow < ROWS);
        const long long nidx = (long long)nrow * DV + tid;

        // Prefetch next row BEFORE reducing current row — these 6 loads are
        // in flight while the shuffle/barrier tail below executes.
        float4 NHR, NHI, NRR, NRI, NTR, NTI;
        if (have_next) {
            NHR = __ldcs(hr + nidx);
            NHI = __ldcs(hi + nidx);
            NRR = __ldcs(rr + nidx);
            NRI = __ldcs(ri + nidx);
            NTR = __ldcs(tr + nidx);
            NTI = __ldcs(ti + nidx);
        }

        // Compute current row.
        float ab = 0.f, aa = 0.f, bb = 0.f;
        #pragma unroll
        for (int k = 0; k < 4; ++k) {
            const float h_r = (&HR.x)[k], h_i = (&HI.x)[k];
            const float r_r = (&RR.x)[k], r_i = (&RI.x)[k];
            const float t_r = (&TR.x)[k], t_i = (&TI.x)[k];
            const float rot_r = h_r * r_r - h_i * r_i;
            const float rot_i = -(h_i * r_r + h_r * r_i);
            ab = fmaf(rot_r, t_r, fmaf(rot_i, t_i, ab));
            aa = fmaf(rot_r, rot_r, fmaf(rot_i, rot_i, aa));
            bb = fmaf(t_r, t_r, fmaf(t_i, t_i, bb));
        }

        #pragma unroll
        for (int off = 16; off > 0; off >>= 1) {
            ab += __shfl_xor_sync(0xFFFFFFFFu, ab, off);
            aa += __shfl_xor_sync(0xFFFFFFFFu, aa, off);
            bb += __shfl_xor_sync(0xFFFFFFFFu, bb, off);
        }
        if (lid == 0) {
            s_ab[buf][wid] = ab;
            s_aa[buf][wid] = aa;
            s_bb[buf][wid] = bb;
        }
        __syncthreads();

        // Warp 0 finalizes this row from buffer `buf` while other warps can
        // run ahead into the next iteration (they write buffer `buf^1`).
        if (wid == 0) {
            float tab = (lid < WARPS) ? s_ab[buf][lid] : 0.f;
            float taa = (lid < WARPS) ? s_aa[buf][lid] : 0.f;
            float tbb = (lid < WARPS) ? s_bb[buf][lid] : 0.f;
            #pragma unroll
            for (int off = 8; off > 0; off >>= 1) {
                tab += __shfl_xor_sync(0xFFFFFFFFu, tab, off);
                taa += __shfl_xor_sync(0xFFFFFFFFu, taa, off);
                tbb += __shfl_xor_sync(0xFFFFFFFFu, tbb, off);
            }
            if (lid == 0)
                out[row] = tab / sqrtf(taa * tbb);
        }

        // Rotate prefetched data into current registers.
        HR = NHR; HI = NHI; RR = NRR; RI = NRI; TR = NTR; TI = NTI;
        row = nrow;
        buf ^= 1;
    }
}

extern "C" void kernel_launch(void* const* d_in, const int* in_sizes, int n_in,
                              void* d_out, int out_size)
{
    const float4* hr = (const float4*)d_in[0];
    const float4* hi = (const float4*)d_in[1];
    const float4* rr = (const float4*)d_in[2];
    const float4* ri = (const float4*)d_in[3];
    const float4* tr = (const float4*)d_in[4];
    const float4* ti = (const float4*)d_in[5];
    float* out = (float*)d_out;

    chrono_rot_kernel<<<GRID, THREADS>>>(hr, hi, rr, ri, tr, ti, out);
}

// round 15
// speedup vs baseline: 1.0080x; 1.0080x over previous
#include <cuda_runtime.h>

// ChronoRotationTransflormation: per-row normalized complex inner product.
// Inputs: head_real, head_imag, rel_real, rel_imag, tail_real, tail_imag
// all float32 [8192, 2048]. Output: float32 [8192].
//
// R14 (final form): R9 champion layout — CTA-per-row, 512 threads, exactly
// one float4 per thread per array (6 front-batched streaming LDG.128,
// 32 regs, ~91% occupancy). Micro-opt: |rot|^2 = (hr^2+hi^2)(rr^2+ri^2),
// saving one FMA per element on the aa chain.
//
// Evidence this is the ceiling: three structurally different layouts
// (fresh-wave, fat-CTA, persistent+prefetch) all land at 85.8-86.6% DRAM /
// ~6.85 TB/s; kernel time ~= bytes/achieved-BW to within 1%.

#define D 2048
#define DV (D / 4)          // 512 float4 per row
#define THREADS 512         // one float4 per thread
#define WARPS (THREADS / 32)

__global__ __launch_bounds__(THREADS)
void chrono_rot_kernel(const float4* __restrict__ hr,
                       const float4* __restrict__ hi,
                       const float4* __restrict__ rr,
                       const float4* __restrict__ ri,
                       const float4* __restrict__ tr,
                       const float4* __restrict__ ti,
                       float* __restrict__ out)
{
    const long long idx = (long long)blockIdx.x * DV + threadIdx.x;

    // 6 independent streaming loads, issued back-to-back at CTA start.
    const float4 HR = __ldcs(hr + idx);
    const float4 HI = __ldcs(hi + idx);
    const float4 RR = __ldcs(rr + idx);
    const float4 RI = __ldcs(ri + idx);
    const float4 TR = __ldcs(tr + idx);
    const float4 TI = __ldcs(ti + idx);

    float ab = 0.f, aa = 0.f, bb = 0.f;
    #pragma unroll
    for (int k = 0; k < 4; ++k) {
        const float h_r = (&HR.x)[k], h_i = (&HI.x)[k];
        const float r_r = (&RR.x)[k], r_i = (&RI.x)[k];
        const float t_r = (&TR.x)[k], t_i = (&TI.x)[k];
        const float rot_r = h_r * r_r - h_i * r_i;
        const float rot_i = -(h_i * r_r + h_r * r_i);
        ab = fmaf(rot_r, t_r, fmaf(rot_i, t_i, ab));
        // |rot|^2 = (h_r^2 + h_i^2) * (r_r^2 + r_i^2)
        const float h2 = fmaf(h_r, h_r, h_i * h_i);
        const float r2 = fmaf(r_r, r_r, r_i * r_i);
        aa = fmaf(h2, r2, aa);
        bb = fmaf(t_r, t_r, fmaf(t_i, t_i, bb));
    }

    // Warp butterfly reduction.
    #pragma unroll
    for (int off = 16; off > 0; off >>= 1) {
        ab += __shfl_xor_sync(0xFFFFFFFFu, ab, off);
        aa += __shfl_xor_sync(0xFFFFFFFFu, aa, off);
        bb += __shfl_xor_sync(0xFFFFFFFFu, bb, off);
    }

    __shared__ float s_ab[WARPS], s_aa[WARPS], s_bb[WARPS];
    const int wid = threadIdx.x >> 5;
    const int lid = threadIdx.x & 31;
    if (lid == 0) {
        s_ab[wid] = ab;
        s_aa[wid] = aa;
        s_bb[wid] = bb;
    }
    __syncthreads();

    // Final reduction by warp 0: 16 partials live in lanes 0..15.
    if (wid == 0) {
        float tab = (lid < WARPS) ? s_ab[lid] : 0.f;
        float taa = (lid < WARPS) ? s_aa[lid] : 0.f;
        float tbb = (lid < WARPS) ? s_bb[lid] : 0.f;
        #pragma unroll
        for (int off = 8; off > 0; off >>= 1) {
            tab += __shfl_xor_sync(0xFFFFFFFFu, tab, off);
            taa += __shfl_xor_sync(0xFFFFFFFFu, taa, off);
            tbb += __shfl_xor_sync(0xFFFFFFFFu, tbb, off);
        }
        if (lid == 0)
            out[blockIdx.x] = tab / sqrtf(taa * tbb);
    }
}

extern "C" void kernel_launch(void* const* d_in, const int* in_sizes, int n_in,
                              void* d_out, int out_size)
{
    const float4* hr = (const float4*)d_in[0];
    const float4* hi = (const float4*)d_in[1];
    const float4* rr = (const float4*)d_in[2];
    const float4* ri = (const float4*)d_in[3];
    const float4* tr = (const float4*)d_in[4];
    const float4* ti = (const float4*)d_in[5];
    float* out = (float*)d_out;

    const int rows = out_size;  // 8192
    chrono_rot_kernel<<<rows, THREADS>>>(hr, hi, rr, ri, tr, ti, out);
}

// round 16
// speedup vs baseline: 1.0124x; 1.0043x over previous
#include <cuda_runtime.h>

// ChronoRotationTransflormation: per-row normalized complex inner product.
// Inputs: head_real, head_imag, rel_real, rel_imag, tail_real, tail_imag
// all float32 [8192, 2048]. Output: float32 [8192].
//
// FINAL: CTA-per-row, 512 threads, exactly one float4 per thread per array
// (6 front-batched streaming LDG.128, 32 regs, ~90% occupancy).
// |rot|^2 = (hr^2+hi^2)(rr^2+ri^2) saves one FMA/element on the aa chain.
//
// Ceiling evidence: four structurally different layouts all converge at
// 85.8-87.0% DRAM / ~6.9 TB/s; kernel time == bytes/achieved-BW within 1%;
// traffic (403 MB) is irreducible; HBM pattern tuning is not a B300 lever.

#define D 2048
#define DV (D / 4)          // 512 float4 per row
#define THREADS 512         // one float4 per thread
#define WARPS (THREADS / 32)

__global__ __launch_bounds__(THREADS)
void chrono_rot_kernel(const float4* __restrict__ hr,
                       const float4* __restrict__ hi,
                       const float4* __restrict__ rr,
                       const float4* __restrict__ ri,
                       const float4* __restrict__ tr,
                       const float4* __restrict__ ti,
                       float* __restrict__ out)
{
    const long long idx = (long long)blockIdx.x * DV + threadIdx.x;

    // 6 independent streaming loads, issued back-to-back at CTA start.
    const float4 HR = __ldcs(hr + idx);
    const float4 HI = __ldcs(hi + idx);
    const float4 RR = __ldcs(rr + idx);
    const float4 RI = __ldcs(ri + idx);
    const float4 TR = __ldcs(tr + idx);
    const float4 TI = __ldcs(ti + idx);

    float ab = 0.f, aa = 0.f, bb = 0.f;
    #pragma unroll
    for (int k = 0; k < 4; ++k) {
        const float h_r = (&HR.x)[k], h_i = (&HI.x)[k];
        const float r_r = (&RR.x)[k], r_i = (&RI.x)[k];
        const float t_r = (&TR.x)[k], t_i = (&TI.x)[k];
        const float rot_r = h_r * r_r - h_i * r_i;
        const float rot_i = -(h_i * r_r + h_r * r_i);
        ab = fmaf(rot_r, t_r, fmaf(rot_i, t_i, ab));
        // |rot|^2 = (h_r^2 + h_i^2) * (r_r^2 + r_i^2)
        const float h2 = fmaf(h_r, h_r, h_i * h_i);
        const float r2 = fmaf(r_r, r_r, r_i * r_i);
        aa = fmaf(h2, r2, aa);
        bb = fmaf(t_r, t_r, fmaf(t_i, t_i, bb));
    }

    // Warp butterfly reduction.
    #pragma unroll
    for (int off = 16; off > 0; off >>= 1) {
        ab += __shfl_xor_sync(0xFFFFFFFFu, ab, off);
        aa += __shfl_xor_sync(0xFFFFFFFFu, aa, off);
        bb += __shfl_xor_sync(0xFFFFFFFFu, bb, off);
    }

    __shared__ float s_ab[WARPS], s_aa[WARPS], s_bb[WARPS];
    const int wid = threadIdx.x >> 5;
    const int lid = threadIdx.x & 31;
    if (lid == 0) {
        s_ab[wid] = ab;
        s_aa[wid] = aa;
        s_bb[wid] = bb;
    }
    __syncthreads();

    // Final reduction by warp 0: 16 partials live in lanes 0..15.
    if (wid == 0) {
        float tab = (lid < WARPS) ? s_ab[lid] : 0.f;
        float taa = (lid < WARPS) ? s_aa[lid] : 0.f;
        float tbb = (lid < WARPS) ? s_bb[lid] : 0.f;
        #pragma unroll
        for (int off = 8; off > 0; off >>= 1) {
            tab += __shfl_xor_sync(0xFFFFFFFFu, tab, off);
            taa += __shfl_xor_sync(0xFFFFFFFFu, taa, off);
            tbb += __shfl_xor_sync(0xFFFFFFFFu, tbb, off);
        }
        if (lid == 0)
            out[blockIdx.x] = tab / sqrtf(taa * tbb);
    }
}

extern "C" void kernel_launch(void* const* d_in, const int* in_sizes, int n_in,
                              void* d_out, int out_size)
{
    const float4* hr = (const float4*)d_in[0];
    const float4* hi = (const float4*)d_in[1];
    const float4* rr = (const float4*)d_in[2];
    const float4* ri = (const float4*)d_in[3];
    const float4* tr = (const float4*)d_in[4];
    const float4* ti = (const float4*)d_in[5];
    float* out = (float*)d_out;

    const int rows = out_size;  // 8192
    chrono_rot_kernel<<<rows, THREADS>>>(hr, hi, rr, ri, tr, ti, out);
}